// round 11
// baseline (speedup 1.0000x reference)
#include <cuda_runtime.h>

#define RES     96
#define EPSF    1e-5f
#define NQUAD   24                   // 4-row bands
#define NTILE   (NQUAD * 3)          // 72 tiles
#define CAPP    (RES * RES / 2)      // 4608 source pairs max

// Global scratch (static — no cudaMalloc).
__device__ float        g_part[NTILE * 2 * 128];
__device__ unsigned int g_tick[NTILE];          // monotone tickets (replay-safe)

// ---- f32x2 helpers ----------------------------------------------------------
__device__ __forceinline__ unsigned long long pk2(float a, float b) {
    unsigned long long r;
    asm("mov.b64 %0, {%1, %2};" : "=l"(r) : "f"(a), "f"(b));
    return r;
}
__device__ __forceinline__ void unpk2(unsigned long long v, float& a, float& b) {
    asm("mov.b64 {%0, %1}, %2;" : "=f"(a), "=f"(b) : "l"(v));
}
#define ADD2(d, a, b) asm("add.rn.f32x2 %0, %1, %2;" : "=l"(d) : "l"(a), "l"(b))
#define MUL2(d, a, b) asm("mul.rn.f32x2 %0, %1, %2;" : "=l"(d) : "l"(a), "l"(b))
#define FMA2(d, a, b, c) \
    asm("fma.rn.f32x2 %0, %1, %2, %3;" : "=l"(d) : "l"(a), "l"(b), "l"(c))

// ---------------------------------------------------------------------------
// 144 blocks x 1024 threads.  Block -> (tile t = bx>>1, K-half h = bx&1).
// Tile = 4 rows x 32 cols (adaptive window).  Lane owns 4 rows at column j
// via two f32x2 accumulators.  Source-pair + paired-reciprocal core:
//   per pair (s0,s1), per row-pair q:  a=den(s0), b=den(s1)
//   acc_q += (w0*b + w1*a) * rcp(a*b)        -> 4 RCP / 8 lane-terms
// SMEM per pair: entA = float4(-bi0,-bj0,-bi1,-bj1)  (1 LDS.128)
//                entW = float4( w0,  w0,  w1,  w1)   (1 LDS.128)
// => 2 LDS / 8 terms: halves the SM-wide LDS crossbar load vs prior rounds.
// K-halves combined via 2-arrival ticket per tile (no spin, no residency need).
// The 2*eps*sqrt(d2) cross term of the reference is dropped
// (relative contribution <= eps/z <= 1e-5 for interior targets).
// ---------------------------------------------------------------------------
__global__ void __launch_bounds__(1024, 1) fused_kernel(
    const float* __restrict__ b, float* __restrict__ out)
{
    extern __shared__ float4 sm[];
    float4* entA = sm;                    // CAPP float4
    float4* entW = sm + CAPP;             // CAPP float4
    __shared__ int   cnts[RES];
    __shared__ int   offs[RES];
    __shared__ int   sK;
    __shared__ float red[32 * 128];       // 32 warps x 128 tile-targets
    __shared__ int   sflag;

    const int tid  = threadIdx.x;
    const int wid  = tid >> 5;
    const int lane = tid & 31;

    // ---------------- Phase 0: zero packed arrays (tail safety) ----------
    for (int t = tid; t < 2 * CAPP; t += 1024)
        sm[t] = make_float4(0.f, 0.f, 0.f, 0.f);

    // ---------------- Phase 1: compaction ----------------
    {
        const int r0 = wid * 3;
        #pragma unroll
        for (int rr = 0; rr < 3; rr++) {
            const int row = r0 + rr;
            int c = 0;
            #pragma unroll
            for (int s = 0; s < 3; s++) {
                float v = b[row * RES + s * 32 + lane];
                c += __popc(__ballot_sync(0xffffffffu, v > 0.0f));
            }
            if (lane == 0) cnts[row] = c;
        }
    }
    __syncthreads();
    if (wid == 0) {                       // exclusive prefix over 96 counts
        int a0 = cnts[lane], a1 = cnts[lane + 32], a2 = cnts[lane + 64];
        int s0 = a0, s1 = a1, s2 = a2;
        #pragma unroll
        for (int d = 1; d < 32; d <<= 1) {
            int t0 = __shfl_up_sync(0xffffffffu, s0, d); if (lane >= d) s0 += t0;
            int t1 = __shfl_up_sync(0xffffffffu, s1, d); if (lane >= d) s1 += t1;
            int t2 = __shfl_up_sync(0xffffffffu, s2, d); if (lane >= d) s2 += t2;
        }
        s1 += __shfl_sync(0xffffffffu, s0, 31);
        s2 += __shfl_sync(0xffffffffu, s1, 31);
        offs[lane]      = s0 - a0;
        offs[lane + 32] = s1 - a1;
        offs[lane + 64] = s2 - a2;
        if (lane == 31) sK = s2;
    }
    __syncthreads();
    {   // scatter: element pos -> pair pos>>1, slot pos&1
        const int r0 = wid * 3;
        #pragma unroll
        for (int rr = 0; rr < 3; rr++) {
            const int row = r0 + rr;
            int p = offs[row];
            #pragma unroll
            for (int s = 0; s < 3; s++) {
                const int col = s * 32 + lane;
                float v = b[row * RES + col];
                unsigned m = __ballot_sync(0xffffffffu, v > 0.0f);
                if (v > 0.0f) {
                    int pos = p + __popc(m & ((1u << lane) - 1u));
                    float* ap = reinterpret_cast<float*>(&entA[pos >> 1]);
                    float* wp = reinterpret_cast<float*>(&entW[pos >> 1]);
                    const int o = (pos & 1) * 2;
                    ap[o]     = -(float)row;
                    ap[o + 1] = -(float)col;
                    wp[o]     = v;
                    wp[o + 1] = v;
                }
                p += __popc(m);
            }
        }
    }
    __syncthreads();

    // ---------------- tile geometry ----------------
    const int t  = blockIdx.x >> 1;       // tile 0..71
    const int h  = blockIdx.x & 1;        // K-half
    const int q  = t / 3;                 // quad 0..23 (rows 4q..4q+3)
    const int g  = t % 3;                 // window 0..2
    const int i0 = 4 * q;

    int dmin = 1000;
    #pragma unroll
    for (int r = 0; r < 4; r++) { int d = i0 + r - 48; if (d < 0) d = -d; if (d < dmin) dmin = d; }
    int vI = 2208 - dmin * dmin; if (vI < 0) vI = 0;
    int wI = (int)sqrtf((float)vI) + 1;   // over-estimate: safe
    int J0 = 48 - wI; if (J0 < 0) J0 = 0;

    const int j  = J0 + 32 * g + lane;    // may exceed 95 (guarded at write)
    const float fj = (float)j;

    // per-lane constants: z per row (reference-faithful f32 path)
    float c_[4];
    {
        const float djc = fj - 48.0f;
        const float dj2 = djc * djc;      // exact integer-valued
        #pragma unroll
        for (int r = 0; r < 4; r++) {
            float dic = (float)(i0 + r) - 48.0f;
            float z   = 48.0f - sqrtf(fmaf(dic, dic, dj2)) + EPSF;
            c_[r] = fmaf(z, z, EPSF * EPSF);
        }
    }
    const unsigned long long c0  = pk2(c_[0], c_[1]);
    const unsigned long long c1  = pk2(c_[2], c_[3]);
    const unsigned long long fiA = pk2((float)i0,     (float)(i0 + 1));
    const unsigned long long fiB = pk2((float)(i0+2), (float)(i0 + 3));
    const unsigned long long fj2 = pk2(fj, fj);

    // rim skip: any interior target in this warp's 4x32 patch? (block-uniform)
    bool any = false;
    {
        const int djq = (j - 48) * (j - 48);
        #pragma unroll
        for (int r = 0; r < 4; r++) {
            const int di = i0 + r - 48;
            if (di * di + djq < 2209) any = true;
        }
    }
    const bool work = __any_sync(0xffffffffu, any);

    const int Kp = (sK + 1) >> 1;
    const int pa = (Kp * h) >> 1;
    const int pb = (Kp * (h + 1)) >> 1;

    unsigned long long accA = pk2(0.f, 0.f);
    unsigned long long accB = pk2(0.f, 0.f);

    // ---------------- Phase 2: 4-row x 2-source paired-reciprocal core ------
    if (work) {
        #pragma unroll 2
        for (int p = pa + wid; p < pb; p += 32) {
            const float4 eA = entA[p];            // (-bi0,-bj0,-bi1,-bj1)
            const float4 eW = entW[p];            // ( w0,  w0,  w1,  w1)
            const unsigned long long A0i = pk2(eA.x, eA.x);
            const unsigned long long A0j = pk2(eA.y, eA.y);
            const unsigned long long A1i = pk2(eA.z, eA.z);
            const unsigned long long A1j = pk2(eA.w, eA.w);
            const unsigned long long W0  = pk2(eW.x, eW.y);
            const unsigned long long W1  = pk2(eW.z, eW.w);

            unsigned long long dj0, dj1;
            ADD2(dj0, fj2, A0j);
            ADD2(dj1, fj2, A1j);

            // row-pair A (rows i0, i0+1)
            unsigned long long d0A, d1A, u0A, u1A, aA, bA, PA, mA, nA;
            ADD2(d0A, fiA, A0i);
            ADD2(d1A, fiA, A1i);
            FMA2(u0A, dj0, dj0, c0);
            FMA2(u1A, dj1, dj1, c0);
            FMA2(aA, d0A, d0A, u0A);
            FMA2(bA, d1A, d1A, u1A);
            MUL2(PA, aA, bA);
            MUL2(mA, W0, bA);
            FMA2(nA, W1, aA, mA);

            // row-pair B (rows i0+2, i0+3)
            unsigned long long d0B, d1B, u0B, u1B, aB, bB, PB, mB, nB;
            ADD2(d0B, fiB, A0i);
            ADD2(d1B, fiB, A1i);
            FMA2(u0B, dj0, dj0, c1);
            FMA2(u1B, dj1, dj1, c1);
            FMA2(aB, d0B, d0B, u0B);
            FMA2(bB, d1B, d1B, u1B);
            MUL2(PB, aB, bB);
            MUL2(mB, W0, bB);
            FMA2(nB, W1, aB, mB);

            float pAl, pAh, pBl, pBh, iAl, iAh, iBl, iBh;
            unpk2(PA, pAl, pAh);
            unpk2(PB, pBl, pBh);
            asm("rcp.approx.ftz.f32 %0, %1;" : "=f"(iAl) : "f"(pAl));
            asm("rcp.approx.ftz.f32 %0, %1;" : "=f"(iAh) : "f"(pAh));
            asm("rcp.approx.ftz.f32 %0, %1;" : "=f"(iBl) : "f"(pBl));
            asm("rcp.approx.ftz.f32 %0, %1;" : "=f"(iBh) : "f"(pBh));
            const unsigned long long invA = pk2(iAl, iAh);
            const unsigned long long invB = pk2(iBl, iBh);

            FMA2(accA, nA, invA, accA);
            FMA2(accB, nB, invB, accB);
        }
    }

    // ---------------- intra-block reduction: 32 warps -> 128 partials -------
    {
        float a0, a1, a2, a3;
        unpk2(accA, a0, a1);
        unpk2(accB, a2, a3);
        red[wid * 128 +  0 + lane] = a0;
        red[wid * 128 + 32 + lane] = a1;
        red[wid * 128 + 64 + lane] = a2;
        red[wid * 128 + 96 + lane] = a3;
    }
    __syncthreads();

    if (tid < 128) {
        float part = 0.0f;
        #pragma unroll 8
        for (int w = 0; w < 32; w++) part += red[w * 128 + tid];
        g_part[(t * 2 + h) * 128 + tid] = part;
    }

    // ---- rim passthrough for uncovered columns (one block per quad) ----
    if (h == 0 && g == 0 && tid < RES && tid < J0) {
        #pragma unroll
        for (int r = 0; r < 4; r++)
            out[(i0 + r) * RES + tid] = b[(i0 + r) * RES + tid];
    }

    __threadfence();                      // publish partials (gpu scope)
    __syncthreads();
    if (tid == 0) {
        unsigned old = atomicAdd(&g_tick[t], 1u);
        sflag = ((old & 1u) == 1u);       // second arrival this launch
        __threadfence();                  // acquire side
    }
    __syncthreads();

    // ---- second-arriving block combines the 2 halves (fixed order) & writes
    if (sflag && tid < 128) {
        float s = __ldcg(&g_part[(t * 2 + 0) * 128 + tid])
                + __ldcg(&g_part[(t * 2 + 1) * 128 + tid]);
        const int row = i0 + (tid >> 5);
        const int col = J0 + 32 * g + (tid & 31);
        if (col < RES) {
            const int di = row - 48, dj = col - 48;
            const float bv = b[row * RES + col];
            out[row * RES + col] = (di * di + dj * dj >= 2209) ? bv : s;
        }
    }
}

// ------------------------------------------------------------------------------
extern "C" void kernel_launch(void* const* d_in, const int* in_sizes, int n_in,
                              void* d_out, int out_size) {
    (void)in_sizes; (void)n_in; (void)out_size;
    const float* b   = (const float*)d_in[0];
    float*       out = (float*)d_out;

    const int smem_bytes = 2 * CAPP * (int)sizeof(float4);  // 147456
    cudaFuncSetAttribute(fused_kernel,
                         cudaFuncAttributeMaxDynamicSharedMemorySize, smem_bytes);

    fused_kernel<<<144, 1024, smem_bytes>>>(b, out);
}